// round 9
// baseline (speedup 1.0000x reference)
#include <cuda_runtime.h>
#include <cstdint>

#define NN 20000     // nodes
#define CI 128       // in channels
#define TT 8         // time steps
#define CO 64        // out channels
#define EE 160000    // edges

// ---------------- scratch (static device globals; no allocation) ----------------
__device__ double   g_sum[CI];
__device__ double   g_sumsq[CI];
__device__ float    g_mean[CI];
__device__ float    g_rs[CI];                 // rsqrt(var + eps)
__device__ unsigned g_bits[NN * 32];          // spike bits: [n][t*4+k], bit l = spike(c=l+32k, t)
__device__ int      g_deg[NN];
__device__ float    g_dinv[NN];
__device__ int      g_rowptr[NN + 1];
__device__ int      g_cursor[NN];
__device__ int      g_col[EE];
__device__ float    g_wgt[EE];
__device__ float    g_y1[(size_t)NN * CO * TT];   // s @ W1^T  [n][d][t]
__device__ float    g_lut[16 * 256 * 128];        // lut[g][m][dcomb]; dcomb<64 -> W0, else W1
__device__ int      g_is64;

// ---------------- init ----------------
__global__ void k_zero() {
    int i = blockIdx.x * blockDim.x + threadIdx.x;
    if (i < CI) { g_sum[i] = 0.0; g_sumsq[i] = 0.0; }
    if (i < NN) g_deg[i] = 0;
}

// Detect int64 vs int32 edge_index: int64 little-endian => every odd 32-bit word
// of the first values is a zero high-half.
__global__ void k_detect(const unsigned* __restrict__ ei) {
    __shared__ int s_nz;
    if (threadIdx.x == 0) s_nz = 0;
    __syncthreads();
    for (int i = threadIdx.x; i < 256; i += blockDim.x)
        if (ei[2 * i + 1] != 0u) atomicOr(&s_nz, 1);
    __syncthreads();
    if (threadIdx.x == 0) g_is64 = (s_nz == 0) ? 1 : 0;
}

// ---------------- BN stats (fp64 accumulate; channel fixed per thread) ----------------
__global__ void k_stats(const float* __restrict__ x) {
    int tid = blockIdx.x * blockDim.x + threadIdx.x;
    int stride = gridDim.x * blockDim.x;   // launch so stride % 128 == 0
    double s = 0.0, q = 0.0;
    for (int r = tid; r < NN * CI; r += stride) {
        const float4* p = (const float4*)(x + (size_t)r * TT);
        float4 a = p[0], b = p[1];
        s += (double)a.x + (double)a.y + (double)a.z + (double)a.w
           + (double)b.x + (double)b.y + (double)b.z + (double)b.w;
        q += (double)a.x * a.x + (double)a.y * a.y + (double)a.z * a.z + (double)a.w * a.w
           + (double)b.x * b.x + (double)b.y * b.y + (double)b.z * b.z + (double)b.w * b.w;
    }
    int c = tid & 127;   // constant per thread because stride % 128 == 0
    atomicAdd(&g_sum[c], s);
    atomicAdd(&g_sumsq[c], q);
}

__global__ void k_final() {
    int c = threadIdx.x;
    if (c < CI) {
        double cnt = (double)NN * (double)TT;
        double m = g_sum[c] / cnt;
        double var = g_sumsq[c] / cnt - m * m;
        g_mean[c] = (float)m;
        g_rs[c] = (float)(1.0 / sqrt(var + 1e-5));
    }
}

// ---------------- LUT build: lut[g][m][d] = sum_{i: bit i of m} W[d][8g+i] ----------------
__global__ void k_lut(const float* __restrict__ W0, const float* __restrict__ W1) {
    int d = threadIdx.x;                  // 0..127 combined output
    int gm = blockIdx.x;                  // g*256 + m
    int g = gm >> 8;
    int m = gm & 255;
    const float* W = (d < CO) ? (W0 + (size_t)d * CI) : (W1 + (size_t)(d - CO) * CI);
    int cb = g * 8;
    float s = 0.f;
#pragma unroll
    for (int i = 0; i < 8; i++)
        if (m & (1 << i)) s += __ldg(&W[cb + i]);
    g_lut[(size_t)gm * 128 + d] = s;
}

// ---------------- normalize + LIF + bit-pack (warp per node) ----------------
__global__ void k_lif(const float* __restrict__ x,
                      const float* __restrict__ gamma,
                      const float* __restrict__ beta) {
    __shared__ float sm[CI], sr[CI], sg[CI], sb[CI];
    int tid = threadIdx.x;
    if (tid < CI) { sm[tid] = g_mean[tid]; sr[tid] = g_rs[tid]; sg[tid] = gamma[tid]; sb[tid] = beta[tid]; }
    __syncthreads();
    int lane = tid & 31;
    int n = blockIdx.x * 8 + (tid >> 5);
    unsigned sp8[4];
#pragma unroll
    for (int k = 0; k < 4; k++) {
        int c = lane + 32 * k;
        const float4* p = (const float4*)(x + (size_t)n * (CI * TT) + (size_t)c * TT);
        float4 a = p[0], b = p[1];
        float m = sm[c], rs = sr[c], ga = sg[c], be = sb[c];
        float h[8];
        // exact reference op order: (gamma*(x-mean))*rsqrt + beta   (no fma contraction)
        h[0] = __fadd_rn(__fmul_rn(__fmul_rn(ga, __fsub_rn(a.x, m)), rs), be);
        h[1] = __fadd_rn(__fmul_rn(__fmul_rn(ga, __fsub_rn(a.y, m)), rs), be);
        h[2] = __fadd_rn(__fmul_rn(__fmul_rn(ga, __fsub_rn(a.z, m)), rs), be);
        h[3] = __fadd_rn(__fmul_rn(__fmul_rn(ga, __fsub_rn(a.w, m)), rs), be);
        h[4] = __fadd_rn(__fmul_rn(__fmul_rn(ga, __fsub_rn(b.x, m)), rs), be);
        h[5] = __fadd_rn(__fmul_rn(__fmul_rn(ga, __fsub_rn(b.y, m)), rs), be);
        h[6] = __fadd_rn(__fmul_rn(__fmul_rn(ga, __fsub_rn(b.z, m)), rs), be);
        h[7] = __fadd_rn(__fmul_rn(__fmul_rn(ga, __fsub_rn(b.w, m)), rs), be);
        float mem = 0.f, spf = 0.f;
        unsigned msk = 0u;
#pragma unroll
        for (int t = 0; t < 8; t++) {
            mem = __fadd_rn(__fmul_rn(__fmul_rn(mem, 0.2f), __fsub_rn(1.f, spf)), h[t]);
            bool s = (mem > 0.5f);
            spf = s ? 1.f : 0.f;
            msk |= (s ? 1u : 0u) << t;
        }
        sp8[k] = msk;
    }
    unsigned myw = 0u;
#pragma unroll
    for (int idx = 0; idx < 32; idx++) {
        unsigned pred = (sp8[idx & 3] >> (idx >> 2)) & 1u;
        unsigned bal = __ballot_sync(0xffffffffu, pred);
        if (lane == idx) myw = bal;
    }
    g_bits[n * 32 + lane] = myw;
}

// ---------------- degree, scan, CSR build ----------------
__global__ void k_deg(const int* __restrict__ ei) {
    int e = blockIdx.x * blockDim.x + threadIdx.x;
    if (e >= EE) return;
    int is64 = g_is64;
    int d = is64 ? ei[2 * (EE + e)] : ei[EE + e];
    atomicAdd(&g_deg[d], 1);
}

__global__ void k_scan() {
    __shared__ int wsum[32];
    __shared__ int s_off;
    int tid = threadIdx.x, lane = tid & 31, w = tid >> 5;
    if (tid == 0) s_off = 0;
    __syncthreads();
    for (int base = 0; base < NN; base += 1024) {
        int i = base + tid;
        int v = (i < NN) ? g_deg[i] : 0;
        int inc = v;
#pragma unroll
        for (int d = 1; d < 32; d <<= 1) {
            int t = __shfl_up_sync(0xffffffffu, inc, d);
            if (lane >= d) inc += t;
        }
        if (lane == 31) wsum[w] = inc;
        __syncthreads();
        if (w == 0) {
            int xv = wsum[lane];
#pragma unroll
            for (int d = 1; d < 32; d <<= 1) {
                int t = __shfl_up_sync(0xffffffffu, xv, d);
                if (lane >= d) xv += t;
            }
            wsum[lane] = xv;
        }
        __syncthreads();
        int off = s_off + (w ? wsum[w - 1] : 0);
        int excl = off + inc - v;
        if (i < NN) {
            g_rowptr[i] = excl;
            g_cursor[i] = excl;
            g_dinv[i] = (v > 0) ? rsqrtf((float)v) : 0.f;
        }
        __syncthreads();
        if (tid == 0) s_off += wsum[31];
        __syncthreads();
    }
    if (threadIdx.x == 0) g_rowptr[NN] = s_off;
}

__global__ void k_csr(const int* __restrict__ ei) {
    int e = blockIdx.x * blockDim.x + threadIdx.x;
    if (e >= EE) return;
    int is64 = g_is64;
    int s = is64 ? ei[2 * e] : ei[e];
    int d = is64 ? ei[2 * (EE + e)] : ei[EE + e];
    int pos = atomicAdd(&g_cursor[d], 1);
    g_col[pos] = s;
    g_wgt[pos] = __fmul_rn(g_dinv[s], g_dinv[d]);
}

// ---------------- GEMM via 8-bit LUT (warp per node) ----------------
// out[n][d][t]      = sum_c s(n,c,t) W0[d][c] + b[d]      (d < 64 half)
// g_y1[n][d][t]     = sum_c s(n,c,t) W1[d][c]             (d >= 64 half)
__global__ void k_gemm(float* __restrict__ out, const float* __restrict__ bias) {
    __shared__ float sbias[CO];
    int tid = threadIdx.x;
    if (tid < CO) sbias[tid] = bias[tid];
    __syncthreads();
    int lane = tid & 31;
    int n = blockIdx.x * 8 + (tid >> 5);
    unsigned myw = g_bits[n * 32 + lane];
    float acc[8][4];
#pragma unroll
    for (int t = 0; t < 8; t++) {
        float ax = 0.f, ay = 0.f, az = 0.f, aw = 0.f;
#pragma unroll
        for (int k = 0; k < 4; k++) {
            unsigned wv = __shfl_sync(0xffffffffu, myw, t * 4 + k);
#pragma unroll
            for (int j = 0; j < 4; j++) {
                unsigned m = (wv >> (8 * j)) & 255u;
                int g = k * 4 + j;
                const float4 v = *(const float4*)(g_lut + ((((unsigned)g << 8) | m) << 7) + (lane << 2));
                ax += v.x; ay += v.y; az += v.z; aw += v.w;
            }
        }
        acc[t][0] = ax; acc[t][1] = ay; acc[t][2] = az; acc[t][3] = aw;
    }
    float* dst;
    float b0, b1, b2, b3;
    if (lane < 16) {
        dst = out + (size_t)n * (CO * TT) + lane * 32;   // d0 = 4*lane, offset d0*8
        b0 = sbias[4 * lane]; b1 = sbias[4 * lane + 1]; b2 = sbias[4 * lane + 2]; b3 = sbias[4 * lane + 3];
    } else {
        dst = g_y1 + (size_t)n * (CO * TT) + (lane - 16) * 32;
        b0 = b1 = b2 = b3 = 0.f;
    }
    float bj[4] = {b0, b1, b2, b3};
#pragma unroll
    for (int j = 0; j < 4; j++) {
        float4 lo = make_float4(acc[0][j] + bj[j], acc[1][j] + bj[j], acc[2][j] + bj[j], acc[3][j] + bj[j]);
        float4 hi = make_float4(acc[4][j] + bj[j], acc[5][j] + bj[j], acc[6][j] + bj[j], acc[7][j] + bj[j]);
        ((float4*)dst)[j * 2] = lo;
        ((float4*)dst)[j * 2 + 1] = hi;
    }
}

// ---------------- atomic-free gather: out[n] += sum_e w_e * y1[src_e] ----------------
__global__ void k_gather(float* __restrict__ out) {
    int n = blockIdx.x;
    int tid = threadIdx.x;   // 128 threads x float4 = 512 floats per node
    int beg = g_rowptr[n], end = g_rowptr[n + 1];
    float4 acc = make_float4(0.f, 0.f, 0.f, 0.f);
    for (int e = beg; e < end; e++) {
        int s = g_col[e];
        float wv = g_wgt[e];
        float4 v = __ldg((const float4*)(g_y1 + (size_t)s * (CO * TT)) + tid);
        acc.x = __fmaf_rn(wv, v.x, acc.x);
        acc.y = __fmaf_rn(wv, v.y, acc.y);
        acc.z = __fmaf_rn(wv, v.z, acc.z);
        acc.w = __fmaf_rn(wv, v.w, acc.w);
    }
    float4* o = (float4*)(out + (size_t)n * (CO * TT)) + tid;
    float4 cur = *o;
    cur.x += acc.x; cur.y += acc.y; cur.z += acc.z; cur.w += acc.w;
    *o = cur;
}

// ---------------- launch ----------------
extern "C" void kernel_launch(void* const* d_in, const int* in_sizes, int n_in,
                              void* d_out, int out_size) {
    const float* x     = (const float*)d_in[0];
    const int*   ei    = (const int*)d_in[1];
    const float* gamma = (const float*)d_in[2];
    const float* beta  = (const float*)d_in[3];
    const float* W0    = (const float*)d_in[4];
    const float* W1    = (const float*)d_in[5];
    const float* bias  = (const float*)d_in[6];
    float* out = (float*)d_out;

    k_zero  <<<(NN + 255) / 256, 256>>>();
    k_detect<<<1, 256>>>((const unsigned*)ei);
    k_stats <<<1024, 256>>>(x);                 // stride 262144 (multiple of 128)
    k_final <<<1, 128>>>();
    k_lut   <<<16 * 256, 128>>>(W0, W1);
    k_lif   <<<NN / 8, 256>>>(x, gamma, beta);
    k_deg   <<<(EE + 255) / 256, 256>>>(ei);
    k_scan  <<<1, 1024>>>();
    k_csr   <<<(EE + 255) / 256, 256>>>(ei);
    k_gemm  <<<NN / 8, 256>>>(out, bias);
    k_gather<<<NN, 128>>>(out);
}

// round 10
// speedup vs baseline: 1.0523x; 1.0523x over previous
#include <cuda_runtime.h>
#include <cuda_bf16.h>
#include <cstdint>

#define NN 20000     // nodes
#define CI 128       // in channels
#define TT 8         // time steps
#define CO 64        // out channels
#define EE 160000    // edges
#define NB 16        // nodes per mma block (128 rows)

// ---------------- scratch (static device globals; no allocation) ----------------
__device__ double   g_sum[CI];
__device__ double   g_sumsq[CI];
__device__ float    g_mean[CI];
__device__ float    g_rs[CI];                 // rsqrt(var + eps)
__device__ unsigned g_bits[NN * 32];          // spike bits: [n][t*4+k], bit l = spike(c=l+32k, t)
__device__ int      g_deg[NN];
__device__ float    g_dinv[NN];
__device__ int      g_rowptr[NN + 1];
__device__ int      g_cursor[NN];
__device__ int      g_col[EE];
__device__ float    g_wgt[EE];
__device__ float    g_y1[(size_t)NN * CO * TT];   // s @ W1^T  [n][d][t]
__device__ uint4    g_Bq[32 * 128];               // split-bf16 weights, swizzled smem layout
__device__ int      g_is64;

// ---------------- init ----------------
__global__ void k_zero() {
    int i = blockIdx.x * blockDim.x + threadIdx.x;
    if (i < CI) { g_sum[i] = 0.0; g_sumsq[i] = 0.0; }
    if (i < NN) g_deg[i] = 0;
}

__global__ void k_detect(const unsigned* __restrict__ ei) {
    __shared__ int s_nz;
    if (threadIdx.x == 0) s_nz = 0;
    __syncthreads();
    for (int i = threadIdx.x; i < 256; i += blockDim.x)
        if (ei[2 * i + 1] != 0u) atomicOr(&s_nz, 1);
    __syncthreads();
    if (threadIdx.x == 0) g_is64 = (s_nz == 0) ? 1 : 0;
}

// ---------------- BN stats (fp64 accumulate; channel fixed per thread) ----------------
__global__ void k_stats(const float* __restrict__ x) {
    int tid = blockIdx.x * blockDim.x + threadIdx.x;
    int stride = gridDim.x * blockDim.x;   // stride % 128 == 0
    double s = 0.0, q = 0.0;
    for (int r = tid; r < NN * CI; r += stride) {
        const float4* p = (const float4*)(x + (size_t)r * TT);
        float4 a = p[0], b = p[1];
        s += (double)a.x + (double)a.y + (double)a.z + (double)a.w
           + (double)b.x + (double)b.y + (double)b.z + (double)b.w;
        q += (double)a.x * a.x + (double)a.y * a.y + (double)a.z * a.z + (double)a.w * a.w
           + (double)b.x * b.x + (double)b.y * b.y + (double)b.z * b.z + (double)b.w * b.w;
    }
    int c = tid & 127;
    atomicAdd(&g_sum[c], s);
    atomicAdd(&g_sumsq[c], q);
}

__global__ void k_final() {
    int c = threadIdx.x;
    if (c < CI) {
        double cnt = (double)NN * (double)TT;
        double m = g_sum[c] / cnt;
        double var = g_sumsq[c] / cnt - m * m;
        g_mean[c] = (float)m;
        g_rs[c] = (float)(1.0 / sqrt(var + 1e-5));
    }
}

// ---------------- weight split into hi/lo bf16, MMA-fragment layout, bank-swizzled ----------------
// g_Bq[k2g*128 + (d ^ (tIG<<1))] = {hi(k0),hi(k0+1) | hi(k0+8),hi(k0+9) | lo pair0 | lo pair1}
// where k2g = s*4 + tIG (s = kstep 0..7), k0 = 16*s + 2*tIG, d = combined output col (0..63 W0, 64..127 W1)
__device__ __forceinline__ unsigned pack_hi(float a, float b, float& ra, float& rb) {
    __nv_bfloat16 ha = __float2bfloat16_rn(a);
    __nv_bfloat16 hb = __float2bfloat16_rn(b);
    ra = a - __bfloat162float(ha);
    rb = b - __bfloat162float(hb);
    return (unsigned)__bfloat16_as_ushort(ha) | ((unsigned)__bfloat16_as_ushort(hb) << 16);
}
__device__ __forceinline__ unsigned pack_lo(float a, float b) {
    return (unsigned)__bfloat16_as_ushort(__float2bfloat16_rn(a))
         | ((unsigned)__bfloat16_as_ushort(__float2bfloat16_rn(b)) << 16);
}

__global__ void k_wsplit(const float* __restrict__ W0, const float* __restrict__ W1) {
    int i = blockIdx.x * blockDim.x + threadIdx.x;   // 0..4095
    if (i >= 4096) return;
    int k2g = i >> 7;
    int d   = i & 127;
    int s = k2g >> 2, tIG = k2g & 3;
    int k0 = 16 * s + 2 * tIG;
    const float* W = (d < CO) ? (W0 + (size_t)d * CI) : (W1 + (size_t)(d - CO) * CI);
    float wa = W[k0], wb = W[k0 + 1], wc = W[k0 + 8], wd = W[k0 + 9];
    float ra, rb, rc, rd;
    uint4 v;
    v.x = pack_hi(wa, wb, ra, rb);
    v.y = pack_hi(wc, wd, rc, rd);
    v.z = pack_lo(ra, rb);
    v.w = pack_lo(rc, rd);
    g_Bq[k2g * 128 + (d ^ (tIG << 1))] = v;
}

// ---------------- normalize + LIF + bit-pack (warp per node) ----------------
__global__ void k_lif(const float* __restrict__ x,
                      const float* __restrict__ gamma,
                      const float* __restrict__ beta) {
    __shared__ float sm[CI], sr[CI], sg[CI], sb[CI];
    int tid = threadIdx.x;
    if (tid < CI) { sm[tid] = g_mean[tid]; sr[tid] = g_rs[tid]; sg[tid] = gamma[tid]; sb[tid] = beta[tid]; }
    __syncthreads();
    int lane = tid & 31;
    int n = blockIdx.x * 8 + (tid >> 5);
    unsigned sp8[4];
#pragma unroll
    for (int k = 0; k < 4; k++) {
        int c = lane + 32 * k;
        const float4* p = (const float4*)(x + (size_t)n * (CI * TT) + (size_t)c * TT);
        float4 a = p[0], b = p[1];
        float m = sm[c], rs = sr[c], ga = sg[c], be = sb[c];
        float h[8];
        h[0] = __fadd_rn(__fmul_rn(__fmul_rn(ga, __fsub_rn(a.x, m)), rs), be);
        h[1] = __fadd_rn(__fmul_rn(__fmul_rn(ga, __fsub_rn(a.y, m)), rs), be);
        h[2] = __fadd_rn(__fmul_rn(__fmul_rn(ga, __fsub_rn(a.z, m)), rs), be);
        h[3] = __fadd_rn(__fmul_rn(__fmul_rn(ga, __fsub_rn(a.w, m)), rs), be);
        h[4] = __fadd_rn(__fmul_rn(__fmul_rn(ga, __fsub_rn(b.x, m)), rs), be);
        h[5] = __fadd_rn(__fmul_rn(__fmul_rn(ga, __fsub_rn(b.y, m)), rs), be);
        h[6] = __fadd_rn(__fmul_rn(__fmul_rn(ga, __fsub_rn(b.z, m)), rs), be);
        h[7] = __fadd_rn(__fmul_rn(__fmul_rn(ga, __fsub_rn(b.w, m)), rs), be);
        float mem = 0.f, spf = 0.f;
        unsigned msk = 0u;
#pragma unroll
        for (int t = 0; t < 8; t++) {
            mem = __fadd_rn(__fmul_rn(__fmul_rn(mem, 0.2f), __fsub_rn(1.f, spf)), h[t]);
            bool s = (mem > 0.5f);
            spf = s ? 1.f : 0.f;
            msk |= (s ? 1u : 0u) << t;
        }
        sp8[k] = msk;
    }
    unsigned myw = 0u;
#pragma unroll
    for (int idx = 0; idx < 32; idx++) {
        unsigned pred = (sp8[idx & 3] >> (idx >> 2)) & 1u;
        unsigned bal = __ballot_sync(0xffffffffu, pred);
        if (lane == idx) myw = bal;
    }
    g_bits[n * 32 + lane] = myw;
}

// ---------------- degree, scan, CSR build ----------------
__global__ void k_deg(const int* __restrict__ ei) {
    int e = blockIdx.x * blockDim.x + threadIdx.x;
    if (e >= EE) return;
    int is64 = g_is64;
    int d = is64 ? ei[2 * (EE + e)] : ei[EE + e];
    atomicAdd(&g_deg[d], 1);
}

__global__ void k_scan() {
    __shared__ int wsum[32];
    __shared__ int s_off;
    int tid = threadIdx.x, lane = tid & 31, w = tid >> 5;
    if (tid == 0) s_off = 0;
    __syncthreads();
    for (int base = 0; base < NN; base += 1024) {
        int i = base + tid;
        int v = (i < NN) ? g_deg[i] : 0;
        int inc = v;
#pragma unroll
        for (int d = 1; d < 32; d <<= 1) {
            int t = __shfl_up_sync(0xffffffffu, inc, d);
            if (lane >= d) inc += t;
        }
        if (lane == 31) wsum[w] = inc;
        __syncthreads();
        if (w == 0) {
            int xv = wsum[lane];
#pragma unroll
            for (int d = 1; d < 32; d <<= 1) {
                int t = __shfl_up_sync(0xffffffffu, xv, d);
                if (lane >= d) xv += t;
            }
            wsum[lane] = xv;
        }
        __syncthreads();
        int off = s_off + (w ? wsum[w - 1] : 0);
        int excl = off + inc - v;
        if (i < NN) {
            g_rowptr[i] = excl;
            g_cursor[i] = excl;
            g_dinv[i] = (v > 0) ? rsqrtf((float)v) : 0.f;
        }
        __syncthreads();
        if (tid == 0) s_off += wsum[31];
        __syncthreads();
    }
    if (threadIdx.x == 0) g_rowptr[NN] = s_off;
}

__global__ void k_csr(const int* __restrict__ ei) {
    int e = blockIdx.x * blockDim.x + threadIdx.x;
    if (e >= EE) return;
    int is64 = g_is64;
    int s = is64 ? ei[2 * e] : ei[e];
    int d = is64 ? ei[2 * (EE + e)] : ei[EE + e];
    int pos = atomicAdd(&g_cursor[d], 1);
    g_col[pos] = s;
    g_wgt[pos] = __fmul_rn(g_dinv[s], g_dinv[d]);
}

// ---------------- tensor-core GEMM: spikes (bf16 0/1) x split-bf16 weights ----------------
// C[r=(n,t), d] = sum_c s(n,c,t) * W(d,c);  d<64 -> out (+bias), d>=64 -> g_y1
__device__ __forceinline__ unsigned pk(unsigned t) {
    // bits 0,1 -> packed bf16x2 {1.0 or 0.0, 1.0 or 0.0}
    return ((t & 1u) * 0x3F80u) | ((t & 2u) * 0x1FC00000u);
}

#define MMA16816(c, a, b0, b1)                                               \
    asm volatile(                                                            \
        "mma.sync.aligned.m16n8k16.row.col.f32.bf16.bf16.f32 "               \
        "{%0,%1,%2,%3},{%4,%5,%6,%7},{%8,%9},{%0,%1,%2,%3};"                 \
        : "+f"(c[0]), "+f"(c[1]), "+f"(c[2]), "+f"(c[3])                     \
        : "r"(a[0]), "r"(a[1]), "r"(a[2]), "r"(a[3]), "r"(b0), "r"(b1))

__global__ __launch_bounds__(256) void k_mma(float* __restrict__ out,
                                             const float* __restrict__ bias) {
    extern __shared__ char smem[];
    uint4*    sB    = (uint4*)smem;                 // 32*128 uint4 = 64 KB
    unsigned* sBits = (unsigned*)(sB + 32 * 128);   // 128 rows x 4 words = 2 KB
    float*    sbias = (float*)(sBits + 128 * 4);    // 256 B

    int tid = threadIdx.x;
    int n0 = blockIdx.x * NB;

    for (int i = tid; i < 32 * 128; i += 256) sB[i] = g_Bq[i];
    const unsigned* gb = g_bits + (size_t)n0 * 32;
    for (int i = tid; i < NB * 32; i += 256) sBits[i] = gb[i];
    if (tid < CO) sbias[tid] = bias[tid];
    __syncthreads();

    int w = tid >> 5, lane = tid & 31;
    int g = lane >> 2, tIG = lane & 3;
    int ct = w >> 2;          // col half: 0 -> W0/out, 1 -> W1/y1
    int mp = w & 3;           // m-tile pair -> rows [32*mp, 32*mp+32)
    int rbase = mp * 32;

    float acc[2][8][4];
#pragma unroll
    for (int m = 0; m < 2; m++)
#pragma unroll
        for (int nt = 0; nt < 8; nt++)
#pragma unroll
            for (int j = 0; j < 4; j++) acc[m][nt][j] = 0.f;

#pragma unroll
    for (int s = 0; s < 8; s++) {
        int widx = s >> 1;
        int off = (s & 1) * 16;
        int p = off + 2 * tIG;
        unsigned a[2][4];
#pragma unroll
        for (int m = 0; m < 2; m++) {
            int r0 = rbase + m * 16 + g;
            unsigned w0 = sBits[r0 * 4 + widx];
            unsigned w1 = sBits[(r0 + 8) * 4 + widx];
            a[m][0] = pk(w0 >> p);
            a[m][1] = pk(w1 >> p);
            a[m][2] = pk(w0 >> (p + 8));
            a[m][3] = pk(w1 >> (p + 8));
        }
        int krow = (s * 4 + tIG) * 128;
        int dsw = (ct * 64 + g) ^ (tIG << 1);
#pragma unroll
        for (int nt = 0; nt < 8; nt++) {
            uint4 B = sB[krow + (dsw ^ (nt * 8))];   // nt*8 doesn't touch swizzled low bits
#pragma unroll
            for (int m = 0; m < 2; m++) {
                MMA16816(acc[m][nt], a[m], B.x, B.y);   // hi
                MMA16816(acc[m][nt], a[m], B.z, B.w);   // lo
            }
        }
    }

    // epilogue: C[row, dcomb] -> out[n][d][t] (+bias) or g_y1[n][d][t]
#pragma unroll
    for (int m = 0; m < 2; m++) {
#pragma unroll
        for (int nt = 0; nt < 8; nt++) {
            int cb = ct * 64 + nt * 8 + 2 * tIG;
#pragma unroll
            for (int half = 0; half < 2; half++) {
                int r = rbase + m * 16 + g + half * 8;
                int nl = r >> 3, t = r & 7;
                size_t rowoff = (size_t)(n0 + nl) * (CO * TT) + t;
#pragma unroll
                for (int j = 0; j < 2; j++) {
                    int dcomb = cb + j;
                    float v = acc[m][nt][half * 2 + j];
                    if (ct == 0)
                        out[rowoff + (size_t)dcomb * TT] = v + sbias[dcomb];
                    else
                        g_y1[rowoff + (size_t)(dcomb - CO) * TT] = v;
                }
            }
        }
    }
}

// ---------------- atomic-free gather: out[n] += sum_e w_e * y1[src_e] ----------------
__global__ void k_gather(float* __restrict__ out) {
    int n = blockIdx.x;
    int tid = threadIdx.x;   // 128 threads x float4 = 512 floats per node
    int beg = g_rowptr[n], end = g_rowptr[n + 1];
    float4 acc = make_float4(0.f, 0.f, 0.f, 0.f);
    for (int e = beg; e < end; e++) {
        int s = g_col[e];
        float wv = g_wgt[e];
        float4 v = __ldg((const float4*)(g_y1 + (size_t)s * (CO * TT)) + tid);
        acc.x = __fmaf_rn(wv, v.x, acc.x);
        acc.y = __fmaf_rn(wv, v.y, acc.y);
        acc.z = __fmaf_rn(wv, v.z, acc.z);
        acc.w = __fmaf_rn(wv, v.w, acc.w);
    }
    float4* o = (float4*)(out + (size_t)n * (CO * TT)) + tid;
    float4 cur = *o;
    cur.x += acc.x; cur.y += acc.y; cur.z += acc.z; cur.w += acc.w;
    *o = cur;
}

// ---------------- launch ----------------
extern "C" void kernel_launch(void* const* d_in, const int* in_sizes, int n_in,
                              void* d_out, int out_size) {
    const float* x     = (const float*)d_in[0];
    const int*   ei    = (const int*)d_in[1];
    const float* gamma = (const float*)d_in[2];
    const float* beta  = (const float*)d_in[3];
    const float* W0    = (const float*)d_in[4];
    const float* W1    = (const float*)d_in[5];
    const float* bias  = (const float*)d_in[6];
    float* out = (float*)d_out;

    const int SMEM_MMA = 32 * 128 * 16 + 128 * 4 * 4 + CO * 4;   // 67840 B
    static bool attr_done = false;
    if (!attr_done) {
        cudaFuncSetAttribute(k_mma, cudaFuncAttributeMaxDynamicSharedMemorySize, SMEM_MMA);
        attr_done = true;
    }

    k_zero  <<<(NN + 255) / 256, 256>>>();
    k_detect<<<1, 256>>>((const unsigned*)ei);
    k_stats <<<1024, 256>>>(x);
    k_final <<<1, 128>>>();
    k_wsplit<<<16, 256>>>(W0, W1);
    k_lif   <<<NN / 8, 256>>>(x, gamma, beta);
    k_deg   <<<(EE + 255) / 256, 256>>>(ei);
    k_scan  <<<1, 1024>>>();
    k_csr   <<<(EE + 255) / 256, 256>>>(ei);
    k_mma   <<<NN / NB, 256, SMEM_MMA>>>(out, bias);
    k_gather<<<NN, 128>>>(out);
}

// round 11
// speedup vs baseline: 1.0791x; 1.0254x over previous
#include <cuda_runtime.h>
#include <cuda_bf16.h>
#include <cstdint>

#define NN 20000     // nodes
#define CI 128       // in channels
#define TT 8         // time steps
#define CO 64        // out channels
#define EE 160000    // edges
#define NB 16        // nodes per mma block (128 rows)

// ---------------- scratch (static device globals; no allocation) ----------------
__device__ double   g_sum[CI];
__device__ double   g_sumsq[CI];
__device__ float    g_mean[CI];
__device__ float    g_rs[CI];                 // rsqrt(var + eps)
__device__ unsigned g_bits[NN * 32];          // spike bits: [n][t*4+k], bit l = spike(c=l+32k, t)
__device__ int      g_deg[NN];
__device__ float    g_dinv[NN];
__device__ int      g_rowptr[NN + 1];
__device__ int      g_cursor[NN];
__device__ int      g_col[EE];
__device__ float    g_wgt[EE];
__device__ float    g_y1[(size_t)NN * CO * TT];   // s @ W1^T  [n][d][t]
__device__ uint4    g_Bq[32 * 128];               // split-bf16 weights, swizzled smem layout
__device__ int      g_is64;

// ---------------- init: zero stats/deg + edge dtype detect (merged) ----------------
__global__ void k_init(const unsigned* __restrict__ ei) {
    int i = blockIdx.x * blockDim.x + threadIdx.x;
    if (i < CI) { g_sum[i] = 0.0; g_sumsq[i] = 0.0; }
    if (i < NN) g_deg[i] = 0;
    if (blockIdx.x == 0) {
        __shared__ int s_nz;
        if (threadIdx.x == 0) s_nz = 0;
        __syncthreads();
        for (int j = threadIdx.x; j < 256; j += blockDim.x)
            if (ei[2 * j + 1] != 0u) atomicOr(&s_nz, 1);
        __syncthreads();
        if (threadIdx.x == 0) g_is64 = (s_nz == 0) ? 1 : 0;
    }
}

// ---------------- BN stats (fp64 accumulate; channel fixed per thread) ----------------
__global__ void k_stats(const float* __restrict__ x) {
    int tid = blockIdx.x * blockDim.x + threadIdx.x;
    int stride = gridDim.x * blockDim.x;   // stride % 128 == 0
    double s = 0.0, q = 0.0;
    for (int r = tid; r < NN * CI; r += stride) {
        const float4* p = (const float4*)(x + (size_t)r * TT);
        float4 a = p[0], b = p[1];
        s += (double)a.x + (double)a.y + (double)a.z + (double)a.w
           + (double)b.x + (double)b.y + (double)b.z + (double)b.w;
        q += (double)a.x * a.x + (double)a.y * a.y + (double)a.z * a.z + (double)a.w * a.w
           + (double)b.x * b.x + (double)b.y * b.y + (double)b.z * b.z + (double)b.w * b.w;
    }
    int c = tid & 127;
    atomicAdd(&g_sum[c], s);
    atomicAdd(&g_sumsq[c], q);
}

__global__ void k_final() {
    int c = threadIdx.x;
    if (c < CI) {
        double cnt = (double)NN * (double)TT;
        double m = g_sum[c] / cnt;
        double var = g_sumsq[c] / cnt - m * m;
        g_mean[c] = (float)m;
        g_rs[c] = (float)(1.0 / sqrt(var + 1e-5));
    }
}

// ---------------- weight split into hi/lo bf16, MMA-fragment layout, bank-swizzled ----------------
__device__ __forceinline__ unsigned pack_hi(float a, float b, float& ra, float& rb) {
    __nv_bfloat16 ha = __float2bfloat16_rn(a);
    __nv_bfloat16 hb = __float2bfloat16_rn(b);
    ra = a - __bfloat162float(ha);
    rb = b - __bfloat162float(hb);
    return (unsigned)__bfloat16_as_ushort(ha) | ((unsigned)__bfloat16_as_ushort(hb) << 16);
}
__device__ __forceinline__ unsigned pack_lo(float a, float b) {
    return (unsigned)__bfloat16_as_ushort(__float2bfloat16_rn(a))
         | ((unsigned)__bfloat16_as_ushort(__float2bfloat16_rn(b)) << 16);
}

__global__ void k_wsplit(const float* __restrict__ W0, const float* __restrict__ W1) {
    int i = blockIdx.x * blockDim.x + threadIdx.x;   // 0..4095
    if (i >= 4096) return;
    int k2g = i >> 7;
    int d   = i & 127;
    int s = k2g >> 2, tIG = k2g & 3;
    int k0 = 16 * s + 2 * tIG;
    const float* W = (d < CO) ? (W0 + (size_t)d * CI) : (W1 + (size_t)(d - CO) * CI);
    float wa = W[k0], wb = W[k0 + 1], wc = W[k0 + 8], wd = W[k0 + 9];
    float ra, rb, rc, rd;
    uint4 v;
    v.x = pack_hi(wa, wb, ra, rb);
    v.y = pack_hi(wc, wd, rc, rd);
    v.z = pack_lo(ra, rb);
    v.w = pack_lo(rc, rd);
    g_Bq[k2g * 128 + (d ^ (tIG << 1))] = v;
}

// ---------------- normalize + LIF + bit-pack (warp per node) ----------------
__global__ void k_lif(const float* __restrict__ x,
                      const float* __restrict__ gamma,
                      const float* __restrict__ beta) {
    __shared__ float sm[CI], sr[CI], sg[CI], sb[CI];
    int tid = threadIdx.x;
    if (tid < CI) { sm[tid] = g_mean[tid]; sr[tid] = g_rs[tid]; sg[tid] = gamma[tid]; sb[tid] = beta[tid]; }
    __syncthreads();
    int lane = tid & 31;
    int n = blockIdx.x * 8 + (tid >> 5);
    unsigned sp8[4];
#pragma unroll
    for (int k = 0; k < 4; k++) {
        int c = lane + 32 * k;
        const float4* p = (const float4*)(x + (size_t)n * (CI * TT) + (size_t)c * TT);
        float4 a = p[0], b = p[1];
        float m = sm[c], rs = sr[c], ga = sg[c], be = sb[c];
        float h[8];
        h[0] = __fadd_rn(__fmul_rn(__fmul_rn(ga, __fsub_rn(a.x, m)), rs), be);
        h[1] = __fadd_rn(__fmul_rn(__fmul_rn(ga, __fsub_rn(a.y, m)), rs), be);
        h[2] = __fadd_rn(__fmul_rn(__fmul_rn(ga, __fsub_rn(a.z, m)), rs), be);
        h[3] = __fadd_rn(__fmul_rn(__fmul_rn(ga, __fsub_rn(a.w, m)), rs), be);
        h[4] = __fadd_rn(__fmul_rn(__fmul_rn(ga, __fsub_rn(b.x, m)), rs), be);
        h[5] = __fadd_rn(__fmul_rn(__fmul_rn(ga, __fsub_rn(b.y, m)), rs), be);
        h[6] = __fadd_rn(__fmul_rn(__fmul_rn(ga, __fsub_rn(b.z, m)), rs), be);
        h[7] = __fadd_rn(__fmul_rn(__fmul_rn(ga, __fsub_rn(b.w, m)), rs), be);
        float mem = 0.f, spf = 0.f;
        unsigned msk = 0u;
#pragma unroll
        for (int t = 0; t < 8; t++) {
            mem = __fadd_rn(__fmul_rn(__fmul_rn(mem, 0.2f), __fsub_rn(1.f, spf)), h[t]);
            bool s = (mem > 0.5f);
            spf = s ? 1.f : 0.f;
            msk |= (s ? 1u : 0u) << t;
        }
        sp8[k] = msk;
    }
    unsigned myw = 0u;
#pragma unroll
    for (int idx = 0; idx < 32; idx++) {
        unsigned pred = (sp8[idx & 3] >> (idx >> 2)) & 1u;
        unsigned bal = __ballot_sync(0xffffffffu, pred);
        if (lane == idx) myw = bal;
    }
    g_bits[n * 32 + lane] = myw;
}

// ---------------- degree, scan, CSR build ----------------
__global__ void k_deg(const int* __restrict__ ei) {
    int e = blockIdx.x * blockDim.x + threadIdx.x;
    if (e >= EE) return;
    int is64 = g_is64;
    int d = is64 ? ei[2 * (EE + e)] : ei[EE + e];
    atomicAdd(&g_deg[d], 1);
}

__global__ void k_scan() {
    __shared__ int wsum[32];
    __shared__ int s_off;
    int tid = threadIdx.x, lane = tid & 31, w = tid >> 5;
    if (tid == 0) s_off = 0;
    __syncthreads();
    for (int base = 0; base < NN; base += 1024) {
        int i = base + tid;
        int v = (i < NN) ? g_deg[i] : 0;
        int inc = v;
#pragma unroll
        for (int d = 1; d < 32; d <<= 1) {
            int t = __shfl_up_sync(0xffffffffu, inc, d);
            if (lane >= d) inc += t;
        }
        if (lane == 31) wsum[w] = inc;
        __syncthreads();
        if (w == 0) {
            int xv = wsum[lane];
#pragma unroll
            for (int d = 1; d < 32; d <<= 1) {
                int t = __shfl_up_sync(0xffffffffu, xv, d);
                if (lane >= d) xv += t;
            }
            wsum[lane] = xv;
        }
        __syncthreads();
        int off = s_off + (w ? wsum[w - 1] : 0);
        int excl = off + inc - v;
        if (i < NN) {
            g_rowptr[i] = excl;
            g_cursor[i] = excl;
            g_dinv[i] = (v > 0) ? rsqrtf((float)v) : 0.f;
        }
        __syncthreads();
        if (tid == 0) s_off += wsum[31];
        __syncthreads();
    }
    if (threadIdx.x == 0) g_rowptr[NN] = s_off;
}

__global__ void k_csr(const int* __restrict__ ei) {
    int e = blockIdx.x * blockDim.x + threadIdx.x;
    if (e >= EE) return;
    int is64 = g_is64;
    int s = is64 ? ei[2 * e] : ei[e];
    int d = is64 ? ei[2 * (EE + e)] : ei[EE + e];
    int pos = atomicAdd(&g_cursor[d], 1);
    g_col[pos] = s;
    g_wgt[pos] = __fmul_rn(g_dinv[s], g_dinv[d]);
}

// ---------------- tensor-core GEMM: spikes (bf16 0/1) x split-bf16 weights ----------------
__device__ __forceinline__ unsigned pk(unsigned t) {
    // bits 0,1 -> packed bf16x2 {1.0 or 0.0, 1.0 or 0.0}
    return ((t & 1u) * 0x3F80u) | ((t & 2u) * 0x1FC00000u);
}

#define MMA16816(c, a, b0, b1)                                               \
    asm volatile(                                                            \
        "mma.sync.aligned.m16n8k16.row.col.f32.bf16.bf16.f32 "               \
        "{%0,%1,%2,%3},{%4,%5,%6,%7},{%8,%9},{%0,%1,%2,%3};"                 \
        : "+f"(c[0]), "+f"(c[1]), "+f"(c[2]), "+f"(c[3])                     \
        : "r"(a[0]), "r"(a[1]), "r"(a[2]), "r"(a[3]), "r"(b0), "r"(b1))

#define SC_STRIDE 132   // padded row stride (floats) for the C transpose tile

__global__ __launch_bounds__(256) void k_mma(float* __restrict__ out,
                                             const float* __restrict__ bias) {
    extern __shared__ char smem[];
    uint4*    sB    = (uint4*)smem;                 // 32*128 uint4 = 64 KB (reused as sC)
    unsigned* sBits = (unsigned*)(sB + 32 * 128);   // 128 rows x 4 words = 2 KB
    float*    sbias = (float*)(sBits + 128 * 4);    // 256 B (survives sC reuse)
    float*    sC    = (float*)smem;                 // 128 x SC_STRIDE floats = 67584 B

    int tid = threadIdx.x;
    int n0 = blockIdx.x * NB;

    for (int i = tid; i < 32 * 128; i += 256) sB[i] = g_Bq[i];
    const unsigned* gb = g_bits + (size_t)n0 * 32;
    for (int i = tid; i < NB * 32; i += 256) sBits[i] = gb[i];
    if (tid < CO) sbias[tid] = bias[tid];
    __syncthreads();

    int w = tid >> 5, lane = tid & 31;
    int g = lane >> 2, tIG = lane & 3;
    int ct = w >> 2;          // col half: 0 -> W0/out, 1 -> W1/y1
    int mp = w & 3;           // m-tile pair -> rows [32*mp, 32*mp+32)
    int rbase = mp * 32;

    float acc[2][8][4];
#pragma unroll
    for (int m = 0; m < 2; m++)
#pragma unroll
        for (int nt = 0; nt < 8; nt++)
#pragma unroll
            for (int j = 0; j < 4; j++) acc[m][nt][j] = 0.f;

#pragma unroll
    for (int s = 0; s < 8; s++) {
        int widx = s >> 1;
        int off = (s & 1) * 16;
        int p = off + 2 * tIG;
        unsigned a[2][4];
#pragma unroll
        for (int m = 0; m < 2; m++) {
            int r0 = rbase + m * 16 + g;
            unsigned w0 = sBits[r0 * 4 + widx];
            unsigned w1 = sBits[(r0 + 8) * 4 + widx];
            a[m][0] = pk(w0 >> p);
            a[m][1] = pk(w1 >> p);
            a[m][2] = pk(w0 >> (p + 8));
            a[m][3] = pk(w1 >> (p + 8));
        }
        int krow = (s * 4 + tIG) * 128;
        int dsw = (ct * 64 + g) ^ (tIG << 1);
#pragma unroll
        for (int nt = 0; nt < 8; nt++) {
            uint4 B = sB[krow + (dsw ^ (nt * 8))];
#pragma unroll
            for (int m = 0; m < 2; m++) {
                MMA16816(acc[m][nt], a[m], B.x, B.y);   // hi
                MMA16816(acc[m][nt], a[m], B.z, B.w);   // lo
            }
        }
    }

    // -------- epilogue: transpose through smem, then fully-coalesced float4 stores ----
    __syncthreads();   // sB dead; reuse as sC
#pragma unroll
    for (int m = 0; m < 2; m++)
#pragma unroll
        for (int nt = 0; nt < 8; nt++)
#pragma unroll
            for (int half = 0; half < 2; half++) {
                int r = rbase + m * 16 + g + half * 8;
                int dcomb = ct * 64 + nt * 8 + 2 * tIG;
                *(float2*)(sC + r * SC_STRIDE + dcomb) =
                    make_float2(acc[m][nt][half * 2], acc[m][nt][half * 2 + 1]);
            }
    __syncthreads();

    // 4096 float4 per block: i -> (nl, dcomb, t4); warp covers a contiguous 512B span
    for (int i = tid; i < NB * 128 * 2; i += 256) {
        int nl = i >> 8;
        int rem = i & 255;
        int dcomb = rem >> 1;
        int t4 = rem & 1;
        const float* p = sC + (nl * 8 + t4 * 4) * SC_STRIDE + dcomb;
        float4 v = make_float4(p[0], p[SC_STRIDE], p[2 * SC_STRIDE], p[3 * SC_STRIDE]);
        size_t off = (size_t)(n0 + nl) * (CO * TT) + t4 * 4;
        if (dcomb < CO) {
            float bv = sbias[dcomb];
            v.x += bv; v.y += bv; v.z += bv; v.w += bv;
            *(float4*)(out + off + (size_t)dcomb * TT) = v;
        } else {
            *(float4*)(g_y1 + off + (size_t)(dcomb - CO) * TT) = v;
        }
    }
}

// ---------------- atomic-free gather: out[n] += sum_e w_e * y1[src_e] ----------------
__global__ void k_gather(float* __restrict__ out) {
    int n = blockIdx.x;
    int tid = threadIdx.x;   // 128 threads x float4 = 512 floats per node
    int beg = g_rowptr[n], end = g_rowptr[n + 1];
    float4 acc = make_float4(0.f, 0.f, 0.f, 0.f);
    for (int e = beg; e < end; e++) {
        int s = g_col[e];
        float wv = g_wgt[e];
        float4 v = __ldg((const float4*)(g_y1 + (size_t)s * (CO * TT)) + tid);
        acc.x = __fmaf_rn(wv, v.x, acc.x);
        acc.y = __fmaf_rn(wv, v.y, acc.y);
        acc.z = __fmaf_rn(wv, v.z, acc.z);
        acc.w = __fmaf_rn(wv, v.w, acc.w);
    }
    float4* o = (float4*)(out + (size_t)n * (CO * TT)) + tid;
    float4 cur = *o;
    cur.x += acc.x; cur.y += acc.y; cur.z += acc.z; cur.w += acc.w;
    *o = cur;
}

// ---------------- launch ----------------
extern "C" void kernel_launch(void* const* d_in, const int* in_sizes, int n_in,
                              void* d_out, int out_size) {
    const float* x     = (const float*)d_in[0];
    const int*   ei    = (const int*)d_in[1];
    const float* gamma = (const float*)d_in[2];
    const float* beta  = (const float*)d_in[3];
    const float* W0    = (const float*)d_in[4];
    const float* W1    = (const float*)d_in[5];
    const float* bias  = (const float*)d_in[6];
    float* out = (float*)d_out;

    const int SMEM_MMA = 32 * 128 * 16 + 128 * 4 * 4 + CO * 4;   // 67840 B (sC fits in sB+sBits)
    static bool attr_done = false;
    if (!attr_done) {
        cudaFuncSetAttribute(k_mma, cudaFuncAttributeMaxDynamicSharedMemorySize, SMEM_MMA);
        attr_done = true;
    }

    k_init  <<<(NN + 255) / 256, 256>>>((const unsigned*)ei);
    k_stats <<<1024, 256>>>(x);
    k_final <<<1, 128>>>();
    k_wsplit<<<16, 256>>>(W0, W1);
    k_lif   <<<NN / 8, 256>>>(x, gamma, beta);
    k_deg   <<<(EE + 255) / 256, 256>>>(ei);
    k_scan  <<<1, 1024>>>();
    k_csr   <<<(EE + 255) / 256, 256>>>(ei);
    k_mma   <<<NN / NB, 256, SMEM_MMA>>>(out, bias);
    k_gather<<<NN, 128>>>(out);
}

// round 12
// speedup vs baseline: 1.4299x; 1.3251x over previous
#include <cuda_runtime.h>
#include <cuda_bf16.h>
#include <cstdint>

#define NN 20000     // nodes
#define CI 128       // in channels
#define TT 8         // time steps
#define CO 64        // out channels
#define EE 160000    // edges
#define NB 16        // nodes per mma block (128 rows)
#define SBLK 256     // stats blocks

// ---------------- scratch (static device globals; no allocation) ----------------
__device__ double   g_partS[SBLK * CI];
__device__ double   g_partQ[SBLK * CI];
__device__ float    g_mean[CI];
__device__ float    g_rs[CI];                 // rsqrt(var + eps)
__device__ unsigned g_bits[NN * 32];          // spike bits: [n][t*4+k], bit l = spike(c=l+32k, t)
__device__ int      g_deg[NN];
__device__ float    g_dinv[NN];
__device__ int      g_rowptr[NN + 1];
__device__ int      g_cursor[NN];
__device__ int      g_col[EE];
__device__ float    g_wgt[EE];
__device__ float    g_y1[(size_t)NN * CO * TT];   // s @ W1^T  [n][d][t]
__device__ uint4    g_Bq[32 * 128];               // split-bf16 weights, swizzled smem layout
__device__ int      g_is64;

// ---------------- weight split helpers ----------------
__device__ __forceinline__ unsigned pack_hi(float a, float b, float& ra, float& rb) {
    __nv_bfloat16 ha = __float2bfloat16_rn(a);
    __nv_bfloat16 hb = __float2bfloat16_rn(b);
    ra = a - __bfloat162float(ha);
    rb = b - __bfloat162float(hb);
    return (unsigned)__bfloat16_as_ushort(ha) | ((unsigned)__bfloat16_as_ushort(hb) << 16);
}
__device__ __forceinline__ unsigned pack_lo(float a, float b) {
    return (unsigned)__bfloat16_as_ushort(__float2bfloat16_rn(a))
         | ((unsigned)__bfloat16_as_ushort(__float2bfloat16_rn(b)) << 16);
}

// ---------------- init: zero deg + edge dtype detect + weight split (merged) ----------------
// blocks 0..78: zero g_deg (block 0 also runs detect); blocks 79..94: wsplit
__global__ void k_init(const unsigned* __restrict__ ei,
                       const float* __restrict__ W0, const float* __restrict__ W1) {
    int b = blockIdx.x;
    if (b < 79) {
        int i = b * 256 + threadIdx.x;
        if (i < NN) g_deg[i] = 0;
        if (b == 0) {
            __shared__ int s_nz;
            if (threadIdx.x == 0) s_nz = 0;
            __syncthreads();
            for (int j = threadIdx.x; j < 256; j += blockDim.x)
                if (ei[2 * j + 1] != 0u) atomicOr(&s_nz, 1);
            __syncthreads();
            if (threadIdx.x == 0) g_is64 = (s_nz == 0) ? 1 : 0;
        }
    } else {
        int i = (b - 79) * 256 + threadIdx.x;   // 0..4095
        int k2g = i >> 7;
        int d   = i & 127;
        int s = k2g >> 2, tIG = k2g & 3;
        int k0 = 16 * s + 2 * tIG;
        const float* W = (d < CO) ? (W0 + (size_t)d * CI) : (W1 + (size_t)(d - CO) * CI);
        float wa = W[k0], wb = W[k0 + 1], wc = W[k0 + 8], wd = W[k0 + 9];
        float ra, rb, rc, rd;
        uint4 v;
        v.x = pack_hi(wa, wb, ra, rb);
        v.y = pack_hi(wc, wd, rc, rd);
        v.z = pack_lo(ra, rb);
        v.w = pack_lo(rc, rd);
        g_Bq[k2g * 128 + (d ^ (tIG << 1))] = v;
    }
}

// ---------------- BN stats v2: fp32 row partials, fp64 per-thread accum, NO atomics ----------------
__global__ void k_stats(const float* __restrict__ x) {
    int tid = blockIdx.x * 256 + threadIdx.x;
    const int stride = SBLK * 256;   // 65536, % 128 == 0 -> channel fixed per thread
    double s = 0.0, q = 0.0;
    for (int r = tid; r < NN * CI; r += stride) {
        const float4* p = (const float4*)(x + (size_t)r * TT);
        float4 a = p[0], b = p[1];
        float s0 = ((a.x + a.y) + (a.z + a.w)) + ((b.x + b.y) + (b.z + b.w));
        float q0 = ((a.x * a.x + a.y * a.y) + (a.z * a.z + a.w * a.w))
                 + ((b.x * b.x + b.y * b.y) + (b.z * b.z + b.w * b.w));
        s += (double)s0;
        q += (double)q0;
    }
    __shared__ double shS[256], shQ[256];
    shS[threadIdx.x] = s;
    shQ[threadIdx.x] = q;
    __syncthreads();
    if (threadIdx.x < 128) {
        int c = threadIdx.x;   // channel = tid & 127; pair partner is +128
        g_partS[blockIdx.x * CI + c] = shS[c] + shS[c + 128];
        g_partQ[blockIdx.x * CI + c] = shQ[c] + shQ[c + 128];
    }
}

__global__ void k_final() {
    int tid = threadIdx.x;          // 1024 threads: 8 per channel
    int c = tid >> 3, j = tid & 7;
    double s = 0.0, q = 0.0;
    for (int b = j; b < SBLK; b += 8) {
        s += g_partS[b * CI + c];
        q += g_partQ[b * CI + c];
    }
#pragma unroll
    for (int o = 4; o; o >>= 1) {
        s += __shfl_down_sync(0xffffffffu, s, o);
        q += __shfl_down_sync(0xffffffffu, q, o);
    }
    if (j == 0) {
        double cnt = (double)NN * (double)TT;
        double m = s / cnt;
        double var = q / cnt - m * m;
        g_mean[c] = (float)m;
        g_rs[c] = (float)(1.0 / sqrt(var + 1e-5));
    }
}

// ---------------- normalize + LIF + bit-pack (warp per node) ----------------
__global__ void k_lif(const float* __restrict__ x,
                      const float* __restrict__ gamma,
                      const float* __restrict__ beta) {
    __shared__ float sm[CI], sr[CI], sg[CI], sb[CI];
    int tid = threadIdx.x;
    if (tid < CI) { sm[tid] = g_mean[tid]; sr[tid] = g_rs[tid]; sg[tid] = gamma[tid]; sb[tid] = beta[tid]; }
    __syncthreads();
    int lane = tid & 31;
    int n = blockIdx.x * 8 + (tid >> 5);
    unsigned sp8[4];
#pragma unroll
    for (int k = 0; k < 4; k++) {
        int c = lane + 32 * k;
        const float4* p = (const float4*)(x + (size_t)n * (CI * TT) + (size_t)c * TT);
        float4 a = p[0], b = p[1];
        float m = sm[c], rs = sr[c], ga = sg[c], be = sb[c];
        float h[8];
        h[0] = __fadd_rn(__fmul_rn(__fmul_rn(ga, __fsub_rn(a.x, m)), rs), be);
        h[1] = __fadd_rn(__fmul_rn(__fmul_rn(ga, __fsub_rn(a.y, m)), rs), be);
        h[2] = __fadd_rn(__fmul_rn(__fmul_rn(ga, __fsub_rn(a.z, m)), rs), be);
        h[3] = __fadd_rn(__fmul_rn(__fmul_rn(ga, __fsub_rn(a.w, m)), rs), be);
        h[4] = __fadd_rn(__fmul_rn(__fmul_rn(ga, __fsub_rn(b.x, m)), rs), be);
        h[5] = __fadd_rn(__fmul_rn(__fmul_rn(ga, __fsub_rn(b.y, m)), rs), be);
        h[6] = __fadd_rn(__fmul_rn(__fmul_rn(ga, __fsub_rn(b.z, m)), rs), be);
        h[7] = __fadd_rn(__fmul_rn(__fmul_rn(ga, __fsub_rn(b.w, m)), rs), be);
        float mem = 0.f, spf = 0.f;
        unsigned msk = 0u;
#pragma unroll
        for (int t = 0; t < 8; t++) {
            mem = __fadd_rn(__fmul_rn(__fmul_rn(mem, 0.2f), __fsub_rn(1.f, spf)), h[t]);
            bool s = (mem > 0.5f);
            spf = s ? 1.f : 0.f;
            msk |= (s ? 1u : 0u) << t;
        }
        sp8[k] = msk;
    }
    unsigned myw = 0u;
#pragma unroll
    for (int idx = 0; idx < 32; idx++) {
        unsigned pred = (sp8[idx & 3] >> (idx >> 2)) & 1u;
        unsigned bal = __ballot_sync(0xffffffffu, pred);
        if (lane == idx) myw = bal;
    }
    g_bits[n * 32 + lane] = myw;
}

// ---------------- degree, scan, CSR build ----------------
__global__ void k_deg(const int* __restrict__ ei) {
    int e = blockIdx.x * blockDim.x + threadIdx.x;
    if (e >= EE) return;
    int is64 = g_is64;
    int d = is64 ? ei[2 * (EE + e)] : ei[EE + e];
    atomicAdd(&g_deg[d], 1);
}

__global__ void k_scan() {
    __shared__ int wsum[32];
    __shared__ int s_off;
    int tid = threadIdx.x, lane = tid & 31, w = tid >> 5;
    if (tid == 0) s_off = 0;
    __syncthreads();
    for (int base = 0; base < NN; base += 1024) {
        int i = base + tid;
        int v = (i < NN) ? g_deg[i] : 0;
        int inc = v;
#pragma unroll
        for (int d = 1; d < 32; d <<= 1) {
            int t = __shfl_up_sync(0xffffffffu, inc, d);
            if (lane >= d) inc += t;
        }
        if (lane == 31) wsum[w] = inc;
        __syncthreads();
        if (w == 0) {
            int xv = wsum[lane];
#pragma unroll
            for (int d = 1; d < 32; d <<= 1) {
                int t = __shfl_up_sync(0xffffffffu, xv, d);
                if (lane >= d) xv += t;
            }
            wsum[lane] = xv;
        }
        __syncthreads();
        int off = s_off + (w ? wsum[w - 1] : 0);
        int excl = off + inc - v;
        if (i < NN) {
            g_rowptr[i] = excl;
            g_cursor[i] = excl;
            g_dinv[i] = (v > 0) ? rsqrtf((float)v) : 0.f;
        }
        __syncthreads();
        if (tid == 0) s_off += wsum[31];
        __syncthreads();
    }
    if (threadIdx.x == 0) g_rowptr[NN] = s_off;
}

__global__ void k_csr(const int* __restrict__ ei) {
    int e = blockIdx.x * blockDim.x + threadIdx.x;
    if (e >= EE) return;
    int is64 = g_is64;
    int s = is64 ? ei[2 * e] : ei[e];
    int d = is64 ? ei[2 * (EE + e)] : ei[EE + e];
    int pos = atomicAdd(&g_cursor[d], 1);
    g_col[pos] = s;
    g_wgt[pos] = __fmul_rn(g_dinv[s], g_dinv[d]);
}

// ---------------- tensor-core GEMM: spikes (bf16 0/1) x split-bf16 weights ----------------
__device__ __forceinline__ unsigned pk(unsigned t) {
    return ((t & 1u) * 0x3F80u) | ((t & 2u) * 0x1FC00000u);
}

#define MMA16816(c, a, b0, b1)                                               \
    asm volatile(                                                            \
        "mma.sync.aligned.m16n8k16.row.col.f32.bf16.bf16.f32 "               \
        "{%0,%1,%2,%3},{%4,%5,%6,%7},{%8,%9},{%0,%1,%2,%3};"                 \
        : "+f"(c[0]), "+f"(c[1]), "+f"(c[2]), "+f"(c[3])                     \
        : "r"(a[0]), "r"(a[1]), "r"(a[2]), "r"(a[3]), "r"(b0), "r"(b1))

#define SC_STRIDE 132

__global__ __launch_bounds__(256) void k_mma(float* __restrict__ out,
                                             const float* __restrict__ bias) {
    extern __shared__ char smem[];
    uint4*    sB    = (uint4*)smem;                 // 64 KB (reused as sC)
    unsigned* sBits = (unsigned*)(sB + 32 * 128);   // 2 KB
    float*    sbias = (float*)(sBits + 128 * 4);    // 256 B (survives sC reuse)
    float*    sC    = (float*)smem;                 // 128 x SC_STRIDE floats

    int tid = threadIdx.x;
    int n0 = blockIdx.x * NB;

    for (int i = tid; i < 32 * 128; i += 256) sB[i] = g_Bq[i];
    const unsigned* gb = g_bits + (size_t)n0 * 32;
    for (int i = tid; i < NB * 32; i += 256) sBits[i] = gb[i];
    if (tid < CO) sbias[tid] = bias[tid];
    __syncthreads();

    int w = tid >> 5, lane = tid & 31;
    int g = lane >> 2, tIG = lane & 3;
    int ct = w >> 2;
    int mp = w & 3;
    int rbase = mp * 32;

    float acc[2][8][4];
#pragma unroll
    for (int m = 0; m < 2; m++)
#pragma unroll
        for (int nt = 0; nt < 8; nt++)
#pragma unroll
            for (int j = 0; j < 4; j++) acc[m][nt][j] = 0.f;

#pragma unroll
    for (int s = 0; s < 8; s++) {
        int widx = s >> 1;
        int off = (s & 1) * 16;
        int p = off + 2 * tIG;
        unsigned a[2][4];
#pragma unroll
        for (int m = 0; m < 2; m++) {
            int r0 = rbase + m * 16 + g;
            unsigned w0 = sBits[r0 * 4 + widx];
            unsigned w1 = sBits[(r0 + 8) * 4 + widx];
            a[m][0] = pk(w0 >> p);
            a[m][1] = pk(w1 >> p);
            a[m][2] = pk(w0 >> (p + 8));
            a[m][3] = pk(w1 >> (p + 8));
        }
        int krow = (s * 4 + tIG) * 128;
        int dsw = (ct * 64 + g) ^ (tIG << 1);
#pragma unroll
        for (int nt = 0; nt < 8; nt++) {
            uint4 B = sB[krow + (dsw ^ (nt * 8))];
#pragma unroll
            for (int m = 0; m < 2; m++) {
                MMA16816(acc[m][nt], a[m], B.x, B.y);   // hi
                MMA16816(acc[m][nt], a[m], B.z, B.w);   // lo
            }
        }
    }

    __syncthreads();   // sB dead; reuse as sC
#pragma unroll
    for (int m = 0; m < 2; m++)
#pragma unroll
        for (int nt = 0; nt < 8; nt++)
#pragma unroll
            for (int half = 0; half < 2; half++) {
                int r = rbase + m * 16 + g + half * 8;
                int dcomb = ct * 64 + nt * 8 + 2 * tIG;
                *(float2*)(sC + r * SC_STRIDE + dcomb) =
                    make_float2(acc[m][nt][half * 2], acc[m][nt][half * 2 + 1]);
            }
    __syncthreads();

    for (int i = tid; i < NB * 128 * 2; i += 256) {
        int nl = i >> 8;
        int rem = i & 255;
        int dcomb = rem >> 1;
        int t4 = rem & 1;
        const float* p = sC + (nl * 8 + t4 * 4) * SC_STRIDE + dcomb;
        float4 v = make_float4(p[0], p[SC_STRIDE], p[2 * SC_STRIDE], p[3 * SC_STRIDE]);
        size_t off = (size_t)(n0 + nl) * (CO * TT) + t4 * 4;
        if (dcomb < CO) {
            float bv = sbias[dcomb];
            v.x += bv; v.y += bv; v.z += bv; v.w += bv;
            *(float4*)(out + off + (size_t)dcomb * TT) = v;
        } else {
            *(float4*)(g_y1 + off + (size_t)(dcomb - CO) * TT) = v;
        }
    }
}

// ---------------- atomic-free gather, 2 nodes/block, 2-edge unroll ----------------
__global__ __launch_bounds__(256) void k_gather(float* __restrict__ out) {
    int n = blockIdx.x * 2 + (threadIdx.x >> 7);
    int t = threadIdx.x & 127;
    int beg = g_rowptr[n], end = g_rowptr[n + 1];
    float4 a0 = make_float4(0.f, 0.f, 0.f, 0.f);
    float4 a1 = make_float4(0.f, 0.f, 0.f, 0.f);
    int e = beg;
    for (; e + 2 <= end; e += 2) {
        int s0 = g_col[e], s1 = g_col[e + 1];
        float w0 = g_wgt[e], w1 = g_wgt[e + 1];
        float4 v0 = __ldg((const float4*)(g_y1 + (size_t)s0 * (CO * TT)) + t);
        float4 v1 = __ldg((const float4*)(g_y1 + (size_t)s1 * (CO * TT)) + t);
        a0.x = __fmaf_rn(w0, v0.x, a0.x);
        a0.y = __fmaf_rn(w0, v0.y, a0.y);
        a0.z = __fmaf_rn(w0, v0.z, a0.z);
        a0.w = __fmaf_rn(w0, v0.w, a0.w);
        a1.x = __fmaf_rn(w1, v1.x, a1.x);
        a1.y = __fmaf_rn(w1, v1.y, a1.y);
        a1.z = __fmaf_rn(w1, v1.z, a1.z);
        a1.w = __fmaf_rn(w1, v1.w, a1.w);
    }
    if (e < end) {
        int s0 = g_col[e];
        float w0 = g_wgt[e];
        float4 v0 = __ldg((const float4*)(g_y1 + (size_t)s0 * (CO * TT)) + t);
        a0.x = __fmaf_rn(w0, v0.x, a0.x);
        a0.y = __fmaf_rn(w0, v0.y, a0.y);
        a0.z = __fmaf_rn(w0, v0.z, a0.z);
        a0.w = __fmaf_rn(w0, v0.w, a0.w);
    }
    float4* o = (float4*)(out + (size_t)n * (CO * TT)) + t;
    float4 cur = *o;
    cur.x += a0.x + a1.x;
    cur.y += a0.y + a1.y;
    cur.z += a0.z + a1.z;
    cur.w += a0.w + a1.w;
    *o = cur;
}

// ---------------- launch (k_stats placed at index 3 for the ncu window) ----------------
extern "C" void kernel_launch(void* const* d_in, const int* in_sizes, int n_in,
                              void* d_out, int out_size) {
    const float* x     = (const float*)d_in[0];
    const int*   ei    = (const int*)d_in[1];
    const float* gamma = (const float*)d_in[2];
    const float* beta  = (const float*)d_in[3];
    const float* W0    = (const float*)d_in[4];
    const float* W1    = (const float*)d_in[5];
    const float* bias  = (const float*)d_in[6];
    float* out = (float*)d_out;

    const int SMEM_MMA = 32 * 128 * 16 + 128 * 4 * 4 + CO * 4;   // 67840 B
    static bool attr_done = false;
    if (!attr_done) {
        cudaFuncSetAttribute(k_mma, cudaFuncAttributeMaxDynamicSharedMemorySize, SMEM_MMA);
        attr_done = true;
    }

    k_init  <<<95, 256>>>((const unsigned*)ei, W0, W1);   // 0
    k_deg   <<<(EE + 255) / 256, 256>>>(ei);              // 1
    k_scan  <<<1, 1024>>>();                              // 2
    k_stats <<<SBLK, 256>>>(x);                           // 3  <-- profiled
    k_final <<<1, 1024>>>();                              // 4
    k_lif   <<<NN / 8, 256>>>(x, gamma, beta);            // 5
    k_csr   <<<(EE + 255) / 256, 256>>>(ei);              // 6
    k_mma   <<<NN / NB, 256, SMEM_MMA>>>(out, bias);      // 7
    k_gather<<<NN / 2, 256>>>(out);                       // 8
}